// round 9
// baseline (speedup 1.0000x reference)
#include <cuda_runtime.h>
#include <math.h>

#define BDIM 8192
#define CDIM 512
#define SLOTS 32
#define KEY_LR 0.01f

static constexpr float INV_SQRT_C = 0.04419417382415922f;  // 1/sqrt(512)
static constexpr size_t OUT_OFF_OUT = 0;
static constexpr size_t OUT_OFF_M   = (size_t)BDIM * CDIM;
static constexpr size_t OUT_OFF_MK  = OUT_OFF_M + (size_t)BDIM * SLOTS * CDIM;

// Scratch (device globals: no allocations allowed)
__device__ float g_Q   [BDIM * CDIM];
__device__ float g_Kw  [BDIM * CDIM];
__device__ float g_Vw  [BDIM * CDIM];
__device__ float g_G2  [BDIM * CDIM];
__device__ float g_retr[BDIM * CDIM];
__device__ float g_ww  [BDIM * SLOTS];

__device__ __forceinline__ unsigned f2tf(float x) {
    unsigned r;
    asm("cvt.rna.tf32.f32 %0, %1;" : "=r"(r) : "f"(x));
    return r;
}
__device__ __forceinline__ float tfbits(float x) {
    return __uint_as_float(f2tf(x));
}
__device__ __forceinline__ void mma_tf32(float* d, const unsigned* a, const unsigned* b) {
    asm volatile(
        "mma.sync.aligned.m16n8k8.row.col.f32.tf32.tf32.f32 "
        "{%0,%1,%2,%3}, {%4,%5,%6,%7}, {%8,%9}, {%0,%1,%2,%3};"
        : "+f"(d[0]), "+f"(d[1]), "+f"(d[2]), "+f"(d[3])
        : "r"(a[0]), "r"(a[1]), "r"(a[2]), "r"(a[3]), "r"(b[0]), "r"(b[1]));
}

// ---------------------------------------------------------------------------
// Kernel A: Q/K projections (tf32, 256 threads, 128x128 tile, BK=16)
// z=0: Q = h @ Wq^T   z=1: K = pooled @ Wk^T
// ---------------------------------------------------------------------------
__global__ void __launch_bounds__(256)
qk_gemm_kernel(const float* __restrict__ h,
               const float* __restrict__ pooled,
               const float* __restrict__ Wq,
               const float* __restrict__ Wk)
{
    const int mode = blockIdx.z;
    const float* X = (mode == 0) ? h : pooled;
    const float* W = (mode == 0) ? Wq : Wk;
    float* outp    = (mode == 0) ? g_Q : g_Kw;

    __shared__ float As[16][129];
    __shared__ float Bs[16][129];

    const int t      = threadIdx.x;
    const int lane   = t & 31;
    const int wid    = t >> 5;
    const int wm0    = (wid & 1) * 64;
    const int wn0    = (wid >> 1) * 32;
    const int g      = lane >> 2;
    const int tig    = lane & 3;
    const int row0   = blockIdx.y * 128;
    const int col0   = blockIdx.x * 128;
    const int lr     = t >> 1;
    const int seg    = (t & 1) * 8;

    float d[4][4][4];
    #pragma unroll
    for (int im = 0; im < 4; im++)
        #pragma unroll
        for (int in_ = 0; in_ < 4; in_++)
            #pragma unroll
            for (int r = 0; r < 4; r++) d[im][in_][r] = 0.f;

    const float* Xrow = X + (size_t)(row0 + lr) * CDIM;
    const float* Wrow = W + (size_t)(col0 + lr) * CDIM;

    for (int k0 = 0; k0 < CDIM; k0 += 16) {
        float4 av0 = *(const float4*)&Xrow[k0 + seg];
        float4 av1 = *(const float4*)&Xrow[k0 + seg + 4];
        float4 bv0 = *(const float4*)&Wrow[k0 + seg];
        float4 bv1 = *(const float4*)&Wrow[k0 + seg + 4];
        As[seg + 0][lr] = tfbits(av0.x); As[seg + 1][lr] = tfbits(av0.y);
        As[seg + 2][lr] = tfbits(av0.z); As[seg + 3][lr] = tfbits(av0.w);
        As[seg + 4][lr] = tfbits(av1.x); As[seg + 5][lr] = tfbits(av1.y);
        As[seg + 6][lr] = tfbits(av1.z); As[seg + 7][lr] = tfbits(av1.w);
        Bs[seg + 0][lr] = tfbits(bv0.x); Bs[seg + 1][lr] = tfbits(bv0.y);
        Bs[seg + 2][lr] = tfbits(bv0.z); Bs[seg + 3][lr] = tfbits(bv0.w);
        Bs[seg + 4][lr] = tfbits(bv1.x); Bs[seg + 5][lr] = tfbits(bv1.y);
        Bs[seg + 6][lr] = tfbits(bv1.z); Bs[seg + 7][lr] = tfbits(bv1.w);
        __syncthreads();

        #pragma unroll
        for (int ks = 0; ks < 16; ks += 8) {
            unsigned a[4][4], b[4][2];
            #pragma unroll
            for (int im = 0; im < 4; im++) {
                const int m = wm0 + im * 16 + g;
                a[im][0] = __float_as_uint(As[ks + tig][m]);
                a[im][1] = __float_as_uint(As[ks + tig][m + 8]);
                a[im][2] = __float_as_uint(As[ks + tig + 4][m]);
                a[im][3] = __float_as_uint(As[ks + tig + 4][m + 8]);
            }
            #pragma unroll
            for (int in_ = 0; in_ < 4; in_++) {
                const int n = wn0 + in_ * 8 + g;
                b[in_][0] = __float_as_uint(Bs[ks + tig][n]);
                b[in_][1] = __float_as_uint(Bs[ks + tig + 4][n]);
            }
            #pragma unroll
            for (int im = 0; im < 4; im++)
                #pragma unroll
                for (int in_ = 0; in_ < 4; in_++)
                    mma_tf32(d[im][in_], a[im], b[in_]);
        }
        __syncthreads();
    }

    #pragma unroll
    for (int im = 0; im < 4; im++) {
        const int r = row0 + wm0 + im * 16 + g;
        #pragma unroll
        for (int in_ = 0; in_ < 4; in_++) {
            const int c = col0 + wn0 + in_ * 8 + 2 * tig;
            *(float2*)&outp[(size_t)r * CDIM + c] =
                make_float2(d[im][in_][0], d[im][in_][1]);
            *(float2*)&outp[(size_t)(r + 8) * CDIM + c] =
                make_float2(d[im][in_][2], d[im][in_][3]);
        }
    }
}

// ---------------------------------------------------------------------------
// Kernel B: fused attention + V/G2 projections.
// grid = 8704 CTAs, 512 threads. bid%17==16 -> gemm role (512 CTAs: 256 V
// tiles + 256 G2 tiles, interleaved); else attn role (8192 rows).
// Gemm role: 128x128 tile, BK=16, 16 warps (4x4), warp tile 32x32.
// ---------------------------------------------------------------------------
__global__ void __launch_bounds__(512)
attn_vg2_kernel(const float* __restrict__ h,
                const float* __restrict__ pooled,
                const float* __restrict__ Wv,
                const float* __restrict__ Wgate,
                const float* __restrict__ bgate,
                const float* __restrict__ Min,
                const float* __restrict__ Mk,
                float* __restrict__ out)
{
    const int bid = blockIdx.x;
    const int q17 = bid / 17;
    const int r17 = bid - q17 * 17;
    extern __shared__ float sm[];
    const int tid  = threadIdx.x;
    const int warp = tid >> 5;
    const int lane = tid & 31;

    if (r17 == 16) {
        // ---------------- gemm role: V (even) / G2 (odd) ----------------
        const int gidx = q17;               // 0..511
        const int mode = 2 + (gidx & 1);
        const int tile = gidx >> 1;         // 0..255
        const int row0 = (tile >> 2) << 7;
        const int col0 = (tile & 3) << 7;
        const float* X = pooled;
        const float* W;
        int ldw;
        float* outp;
        if (mode == 2) { W = Wv;            ldw = CDIM;     outp = g_Vw; }
        else           { W = Wgate + CDIM;  ldw = 2 * CDIM; outp = g_G2; }

        float* As = sm;          // [16][129]
        float* Bs = sm + 2064;   // [16][129]

        const int wm0 = (warp & 3) * 32;
        const int wn0 = (warp >> 2) * 32;
        const int g   = lane >> 2;
        const int tig = lane & 3;
        const int lr  = tid >> 2;            // 0..127
        const int seg = (tid & 3) << 2;      // 0,4,8,12

        float d[2][4][4];
        #pragma unroll
        for (int im = 0; im < 2; im++)
            #pragma unroll
            for (int in_ = 0; in_ < 4; in_++)
                #pragma unroll
                for (int r = 0; r < 4; r++) d[im][in_][r] = 0.f;

        const float* Xrow = X + (size_t)(row0 + lr) * CDIM;
        const float* Wrow = W + (size_t)(col0 + lr) * ldw;

        for (int k0 = 0; k0 < CDIM; k0 += 16) {
            float4 av = *(const float4*)&Xrow[k0 + seg];
            float4 bv = *(const float4*)&Wrow[k0 + seg];
            As[(seg + 0) * 129 + lr] = tfbits(av.x);
            As[(seg + 1) * 129 + lr] = tfbits(av.y);
            As[(seg + 2) * 129 + lr] = tfbits(av.z);
            As[(seg + 3) * 129 + lr] = tfbits(av.w);
            Bs[(seg + 0) * 129 + lr] = tfbits(bv.x);
            Bs[(seg + 1) * 129 + lr] = tfbits(bv.y);
            Bs[(seg + 2) * 129 + lr] = tfbits(bv.z);
            Bs[(seg + 3) * 129 + lr] = tfbits(bv.w);
            __syncthreads();

            #pragma unroll
            for (int ks = 0; ks < 16; ks += 8) {
                unsigned a[2][4], b[4][2];
                #pragma unroll
                for (int im = 0; im < 2; im++) {
                    const int m = wm0 + im * 16 + g;
                    a[im][0] = __float_as_uint(As[(ks + tig) * 129 + m]);
                    a[im][1] = __float_as_uint(As[(ks + tig) * 129 + m + 8]);
                    a[im][2] = __float_as_uint(As[(ks + tig + 4) * 129 + m]);
                    a[im][3] = __float_as_uint(As[(ks + tig + 4) * 129 + m + 8]);
                }
                #pragma unroll
                for (int in_ = 0; in_ < 4; in_++) {
                    const int n = wn0 + in_ * 8 + g;
                    b[in_][0] = __float_as_uint(Bs[(ks + tig) * 129 + n]);
                    b[in_][1] = __float_as_uint(Bs[(ks + tig + 4) * 129 + n]);
                }
                #pragma unroll
                for (int im = 0; im < 2; im++)
                    #pragma unroll
                    for (int in_ = 0; in_ < 4; in_++)
                        mma_tf32(d[im][in_], a[im], b[in_]);
            }
            __syncthreads();
        }

        #pragma unroll
        for (int im = 0; im < 2; im++) {
            const int r = row0 + wm0 + im * 16 + g;
            #pragma unroll
            for (int in_ = 0; in_ < 4; in_++) {
                const int c = col0 + wn0 + in_ * 8 + 2 * tig;
                float2 v01 = make_float2(d[im][in_][0], d[im][in_][1]);
                float2 v23 = make_float2(d[im][in_][2], d[im][in_][3]);
                if (mode == 3) {
                    const float b0 = bgate[c], b1 = bgate[c + 1];
                    v01.x += b0; v01.y += b1;
                    v23.x += b0; v23.y += b1;
                }
                *(float2*)&outp[(size_t)r * CDIM + c]       = v01;
                *(float2*)&outp[(size_t)(r + 8) * CDIM + c] = v23;
            }
        }
        return;
    }

    // ---------------- attn role ----------------
    const int b = q17 * 16 + r17;   // 0..8191

    float* sq   = sm;                    // 512
    float* skw  = sm + 512;              // 512
    float* mkc  = sm + 1024;             // 32*512
    float* lq   = sm + 1024 + 16384;     // 32
    float* lk   = lq + 32;               // 32
    float* attn = lk + 32;               // 32
    float* ww   = attn + 32;             // 32

    sq[tid]  = g_Q [(size_t)b * CDIM + tid];
    skw[tid] = g_Kw[(size_t)b * CDIM + tid];
    __syncthreads();

    const float4* sq4  = (const float4*)sq;
    const float4* sk4  = (const float4*)skw;
    float4*       mkc4 = (float4*)mkc;
    const float4* mkrow = (const float4*)(Mk + (size_t)b * SLOTS * CDIM);

    #pragma unroll
    for (int i = 0; i < 2; i++) {
        const int m = warp + 16 * i;
        float dq = 0.f, dk = 0.f;
        #pragma unroll
        for (int j = 0; j < 4; j++) {
            const int g = lane + 32 * j;
            float4 v  = mkrow[m * 128 + g];
            float4 qv = sq4[g];
            float4 kv = sk4[g];
            dq += v.x * qv.x + v.y * qv.y + v.z * qv.z + v.w * qv.w;
            dk += v.x * kv.x + v.y * kv.y + v.z * kv.z + v.w * kv.w;
            mkc4[m * 128 + g] = v;
        }
        #pragma unroll
        for (int o = 16; o > 0; o >>= 1) {
            dq += __shfl_xor_sync(0xffffffffu, dq, o);
            dk += __shfl_xor_sync(0xffffffffu, dk, o);
        }
        if (lane == 0) { lq[m] = dq * INV_SQRT_C; lk[m] = dk * INV_SQRT_C; }
    }
    __syncthreads();

    if (tid < 32) {
        float vq = lq[tid], vk = lk[tid];
        float mq = vq, mk2 = vk;
        #pragma unroll
        for (int o = 16; o > 0; o >>= 1) {
            mq  = fmaxf(mq,  __shfl_xor_sync(0xffffffffu, mq,  o));
            mk2 = fmaxf(mk2, __shfl_xor_sync(0xffffffffu, mk2, o));
        }
        float eq = __expf(vq - mq);
        float ek = __expf(vk - mk2);
        float sumq = eq, sumk = ek;
        #pragma unroll
        for (int o = 16; o > 0; o >>= 1) {
            sumq += __shfl_xor_sync(0xffffffffu, sumq, o);
            sumk += __shfl_xor_sync(0xffffffffu, sumk, o);
        }
        const float a = eq / sumq;
        const float w = ek / sumk;
        attn[tid] = a;
        ww[tid]   = w;
        g_ww[b * SLOTS + tid] = w;
    }
    __syncthreads();

    // Mk_new = Mk + ww*KEY_LR*(write_k - Mk), from SMEM cache
    float4* out_mk4 = (float4*)(out + OUT_OFF_MK + (size_t)b * SLOTS * CDIM);
    for (int idx = tid; idx < SLOTS * 128; idx += 512) {
        const int m = idx >> 7;
        const int g = idx & 127;
        float4 v  = mkc4[idx];
        float4 kv = sk4[g];
        const float w = ww[m] * KEY_LR;
        float4 r;
        r.x = v.x + w * (kv.x - v.x);
        r.y = v.y + w * (kv.y - v.y);
        r.z = v.z + w * (kv.z - v.z);
        r.w = v.w + w * (kv.w - v.w);
        out_mk4[idx] = r;
    }

    // retrieved[c] = sum_m attn[m] * M[b,m,c];  out = h + retrieved
    const float* Mrow = Min + (size_t)b * SLOTS * CDIM;
    float acc = 0.f;
    #pragma unroll
    for (int m = 0; m < SLOTS; m++)
        acc = fmaf(attn[m], Mrow[m * CDIM + tid], acc);
    g_retr[(size_t)b * CDIM + tid] = acc;
    out[OUT_OFF_OUT + (size_t)b * CDIM + tid] =
        h[(size_t)b * CDIM + tid] + acc;
}

// ---------------------------------------------------------------------------
// Kernel C: fused gate GEMM + M update.
// 256 CTAs (4 col-tiles x 64 row-tiles), 256 threads.
// Phase 1: d = retr_tile @ Wg1^T (tf32), u = sig(eta)*sigmoid(d+G2)*(Vw-retr)
//          staged into SMEM (stride 132 to keep float4 alignment + banks).
// Phase 2: stream M block: M_new[b,m,c] = M[b,m,c] + ww[b,m]*u[b,c].
// ---------------------------------------------------------------------------
#define SU_STRIDE 132

__global__ void __launch_bounds__(256)
gate_mup_kernel(const float* __restrict__ Wgate,
                const float* __restrict__ bgate,
                const float* __restrict__ eta,
                const float* __restrict__ Min,
                float* __restrict__ out)
{
    const int bid  = blockIdx.x;           // 0..255
    const int col0 = (bid & 3) << 7;
    const int row0 = (bid >> 2) << 7;

    __shared__ float As[16][129];
    __shared__ float Bs[16][129];
    __shared__ float sww[128 * SLOTS];     // 16 KB
    extern __shared__ float su[];          // 128*132 floats = 67584 B

    const int t    = threadIdx.x;
    const int lane = t & 31;
    const int wid  = t >> 5;
    const int wm0  = (wid & 1) * 64;
    const int wn0  = (wid >> 1) * 32;
    const int g    = lane >> 2;
    const int tig  = lane & 3;
    const int lr   = t >> 1;
    const int seg  = (t & 1) * 8;

    // -------- Phase 1: gate GEMM (X = g_retr, W = Wgate first half) --------
    float d[4][4][4];
    #pragma unroll
    for (int im = 0; im < 4; im++)
        #pragma unroll
        for (int in_ = 0; in_ < 4; in_++)
            #pragma unroll
            for (int r = 0; r < 4; r++) d[im][in_][r] = 0.f;

    const float* Xrow = g_retr + (size_t)(row0 + lr) * CDIM;
    const float* Wrow = Wgate + (size_t)(col0 + lr) * (2 * CDIM);

    for (int k0 = 0; k0 < CDIM; k0 += 16) {
        float4 av0 = *(const float4*)&Xrow[k0 + seg];
        float4 av1 = *(const float4*)&Xrow[k0 + seg + 4];
        float4 bv0 = *(const float4*)&Wrow[k0 + seg];
        float4 bv1 = *(const float4*)&Wrow[k0 + seg + 4];
        As[seg + 0][lr] = tfbits(av0.x); As[seg + 1][lr] = tfbits(av0.y);
        As[seg + 2][lr] = tfbits(av0.z); As[seg + 3][lr] = tfbits(av0.w);
        As[seg + 4][lr] = tfbits(av1.x); As[seg + 5][lr] = tfbits(av1.y);
        As[seg + 6][lr] = tfbits(av1.z); As[seg + 7][lr] = tfbits(av1.w);
        Bs[seg + 0][lr] = tfbits(bv0.x); Bs[seg + 1][lr] = tfbits(bv0.y);
        Bs[seg + 2][lr] = tfbits(bv0.z); Bs[seg + 3][lr] = tfbits(bv0.w);
        Bs[seg + 4][lr] = tfbits(bv1.x); Bs[seg + 5][lr] = tfbits(bv1.y);
        Bs[seg + 6][lr] = tfbits(bv1.z); Bs[seg + 7][lr] = tfbits(bv1.w);
        __syncthreads();

        #pragma unroll
        for (int ks = 0; ks < 16; ks += 8) {
            unsigned a[4][4], b[4][2];
            #pragma unroll
            for (int im = 0; im < 4; im++) {
                const int m = wm0 + im * 16 + g;
                a[im][0] = __float_as_uint(As[ks + tig][m]);
                a[im][1] = __float_as_uint(As[ks + tig][m + 8]);
                a[im][2] = __float_as_uint(As[ks + tig + 4][m]);
                a[im][3] = __float_as_uint(As[ks + tig + 4][m + 8]);
            }
            #pragma unroll
            for (int in_ = 0; in_ < 4; in_++) {
                const int n = wn0 + in_ * 8 + g;
                b[in_][0] = __float_as_uint(Bs[ks + tig][n]);
                b[in_][1] = __float_as_uint(Bs[ks + tig + 4][n]);
            }
            #pragma unroll
            for (int im = 0; im < 4; im++)
                #pragma unroll
                for (int in_ = 0; in_ < 4; in_++)
                    mma_tf32(d[im][in_], a[im], b[in_]);
        }
        __syncthreads();
    }

    // u into SMEM (local tile coords)
    #pragma unroll
    for (int im = 0; im < 4; im++) {
        const int lrow = wm0 + im * 16 + g;
        #pragma unroll
        for (int in_ = 0; in_ < 4; in_++) {
            const int lcol = wn0 + in_ * 8 + 2 * tig;
            const int c    = col0 + lcol;
            const float es0 = 1.f / (1.f + __expf(-eta[c]));
            const float es1 = 1.f / (1.f + __expf(-eta[c + 1]));
            #pragma unroll
            for (int rr = 0; rr < 2; rr++) {
                const int row = row0 + lrow + rr * 8;
                const size_t i0 = (size_t)row * CDIM + c;
                float2 uo;
                {
                    const float logit = d[im][in_][rr * 2 + 0] + g_G2[i0];
                    const float sur   = 1.f / (1.f + __expf(-logit));
                    uo.x = es0 * sur * (g_Vw[i0] - g_retr[i0]);
                }
                {
                    const float logit = d[im][in_][rr * 2 + 1] + g_G2[i0 + 1];
                    const float sur   = 1.f / (1.f + __expf(-logit));
                    uo.y = es1 * sur * (g_Vw[i0 + 1] - g_retr[i0 + 1]);
                }
                *(float2*)&su[(lrow + rr * 8) * SU_STRIDE + lcol] = uo;
            }
        }
    }

    // ww for the 128 rows
    for (int i = t; i < 128 * SLOTS; i += 256) {
        const int b = i >> 5;
        const int m = i & 31;
        sww[i] = g_ww[(row0 + b) * SLOTS + m];
    }
    __syncthreads();

    // -------- Phase 2: stream M block --------
    for (int b = 0; b < 128; b++) {
        const size_t base = ((size_t)(row0 + b) * SLOTS) * CDIM + col0;
        const float* surow = su + b * SU_STRIDE;
        const float* swrow = sww + (b << 5);
        #pragma unroll
        for (int k = 0; k < 4; k++) {
            const int idx = t + (k << 8);        // 0..1023
            const int m   = idx >> 5;            // 0..31
            const int cc  = (idx & 31) << 2;     // 0..124 step 4
            const size_t off = base + (size_t)m * CDIM + cc;
            float4 mv = *(const float4*)&Min[off];
            float4 uv = *(const float4*)&surow[cc];
            const float w = swrow[m];
            float4 r;
            r.x = fmaf(w, uv.x, mv.x);
            r.y = fmaf(w, uv.y, mv.y);
            r.z = fmaf(w, uv.z, mv.z);
            r.w = fmaf(w, uv.w, mv.w);
            *(float4*)&out[OUT_OFF_M + off] = r;
        }
    }
}

// ---------------------------------------------------------------------------
extern "C" void kernel_launch(void* const* d_in, const int* in_sizes, int n_in,
                              void* d_out, int out_size)
{
    (void)in_sizes; (void)n_in; (void)out_size;
    const float* h      = (const float*)d_in[0];
    const float* pooled = (const float*)d_in[1];
    const float* M      = (const float*)d_in[2];
    const float* Mk     = (const float*)d_in[3];
    const float* Wq     = (const float*)d_in[4];
    const float* Wk     = (const float*)d_in[5];
    const float* Wv     = (const float*)d_in[6];
    const float* Wg     = (const float*)d_in[7];
    const float* bg     = (const float*)d_in[8];
    const float* eta    = (const float*)d_in[9];
    float* out = (float*)d_out;

    const int smem_b = (1024 + SLOTS * CDIM + 128) * (int)sizeof(float); // 70144 B
    const int smem_c = 128 * SU_STRIDE * (int)sizeof(float);             // 67584 B
    cudaFuncSetAttribute(attn_vg2_kernel,
                         cudaFuncAttributeMaxDynamicSharedMemorySize, smem_b);
    cudaFuncSetAttribute(gate_mup_kernel,
                         cudaFuncAttributeMaxDynamicSharedMemorySize, smem_c);

    // A) Q, K projections
    dim3 gA(CDIM / 128, BDIM / 128, 2);
    qk_gemm_kernel<<<gA, 256>>>(h, pooled, Wq, Wk);

    // B) fused attention + V/G2 projections
    attn_vg2_kernel<<<8704, 512, smem_b>>>(h, pooled, Wv, Wg, bg, M, Mk, out);

    // C) fused gate GEMM + M update
    gate_mup_kernel<<<256, 256, smem_c>>>(Wg, bg, eta, M, out);
}

// round 12
// speedup vs baseline: 1.3945x; 1.3945x over previous
#include <cuda_runtime.h>
#include <math.h>

#define BDIM 8192
#define CDIM 512
#define SLOTS 32
#define KEY_LR 0.01f

static constexpr float INV_SQRT_C = 0.04419417382415922f;  // 1/sqrt(512)
static constexpr size_t OUT_OFF_OUT = 0;
static constexpr size_t OUT_OFF_M   = (size_t)BDIM * CDIM;
static constexpr size_t OUT_OFF_MK  = OUT_OFF_M + (size_t)BDIM * SLOTS * CDIM;

// Scratch (device globals: no allocations allowed)
__device__ float g_Q   [BDIM * CDIM];
__device__ float g_Kw  [BDIM * CDIM];
__device__ float g_Vw  [BDIM * CDIM];
__device__ float g_G2  [BDIM * CDIM];
__device__ float g_retr[BDIM * CDIM];
__device__ float g_u   [BDIM * CDIM];
__device__ float g_ww  [BDIM * SLOTS];

__device__ __forceinline__ unsigned f2tf(float x) {
    unsigned r;
    asm("cvt.rna.tf32.f32 %0, %1;" : "=r"(r) : "f"(x));
    return r;
}
__device__ __forceinline__ float tfbits(float x) {
    return __uint_as_float(f2tf(x));
}
__device__ __forceinline__ void mma_tf32(float* d, const unsigned* a, const unsigned* b) {
    asm volatile(
        "mma.sync.aligned.m16n8k8.row.col.f32.tf32.tf32.f32 "
        "{%0,%1,%2,%3}, {%4,%5,%6,%7}, {%8,%9}, {%0,%1,%2,%3};"
        : "+f"(d[0]), "+f"(d[1]), "+f"(d[2]), "+f"(d[3])
        : "r"(a[0]), "r"(a[1]), "r"(a[2]), "r"(a[3]), "r"(b[0]), "r"(b[1]));
}

// ---------------------------------------------------------------------------
// TF32 GEMM, double-buffered, conflict-free SMEM (stride 136).
// out[r,c] = sum_k X[r,k] * W[c,k]  (NT, row-major)
// 128x128 CTA tile, BK=16, 256 threads = 8 warps (2x4), warp tile 64x32.
// mode 0: Q   mode 1: K   mode 2: V   mode 3: G2(+bias)
// mode 4: u = sig(eta)*sigmoid(retr@Wg1^T + G2)*(V - retr)
// ---------------------------------------------------------------------------
#define SMS 136          // SMEM row stride (floats): 136 % 32 == 8 -> no conflicts
#define SBUF (16 * SMS)  // one buffer = 2176 floats

__global__ void __launch_bounds__(256, 2)
gemm_tf32_kernel(const float* __restrict__ h,
                 const float* __restrict__ pooled,
                 const float* __restrict__ Wq,
                 const float* __restrict__ Wk,
                 const float* __restrict__ Wv,
                 const float* __restrict__ Wgate,
                 const float* __restrict__ bgate,
                 const float* __restrict__ eta,
                 int mode_base)
{
    const int mode = mode_base + blockIdx.z;

    const float* X;
    const float* W;
    int ldw;
    switch (mode) {
        case 0:  X = h;      W = Wq;           ldw = CDIM;     break;
        case 1:  X = pooled; W = Wk;           ldw = CDIM;     break;
        case 2:  X = pooled; W = Wv;           ldw = CDIM;     break;
        case 3:  X = pooled; W = Wgate + CDIM; ldw = 2 * CDIM; break;
        default: X = g_retr; W = Wgate;        ldw = 2 * CDIM; break;
    }

    __shared__ float As[2 * SBUF];
    __shared__ float Bs[2 * SBUF];

    const int t      = threadIdx.x;
    const int lane   = t & 31;
    const int wid    = t >> 5;
    const int wm0    = (wid & 1) * 64;
    const int wn0    = (wid >> 1) * 32;
    const int g      = lane >> 2;      // 0..7
    const int tig    = lane & 3;       // 0..3
    const int row0   = blockIdx.y * 128;
    const int col0   = blockIdx.x * 128;
    const int lr     = t >> 1;         // 0..127
    const int seg    = (t & 1) * 8;    // 0 or 8

    float d[4][4][4];
    #pragma unroll
    for (int im = 0; im < 4; im++)
        #pragma unroll
        for (int in_ = 0; in_ < 4; in_++)
            #pragma unroll
            for (int r = 0; r < 4; r++) d[im][in_][r] = 0.f;

    const float* Xrow = X + (size_t)(row0 + lr) * CDIM;
    const float* Wrow = W + (size_t)(col0 + lr) * ldw;

    float* Ac = As;          float* Bc = Bs;
    float* An = As + SBUF;   float* Bn = Bs + SBUF;

    // Prologue: fill buffer 0 with k0 = 0
    {
        float4 av0 = *(const float4*)&Xrow[seg];
        float4 av1 = *(const float4*)&Xrow[seg + 4];
        float4 bv0 = *(const float4*)&Wrow[seg];
        float4 bv1 = *(const float4*)&Wrow[seg + 4];
        Ac[(seg + 0) * SMS + lr] = tfbits(av0.x);
        Ac[(seg + 1) * SMS + lr] = tfbits(av0.y);
        Ac[(seg + 2) * SMS + lr] = tfbits(av0.z);
        Ac[(seg + 3) * SMS + lr] = tfbits(av0.w);
        Ac[(seg + 4) * SMS + lr] = tfbits(av1.x);
        Ac[(seg + 5) * SMS + lr] = tfbits(av1.y);
        Ac[(seg + 6) * SMS + lr] = tfbits(av1.z);
        Ac[(seg + 7) * SMS + lr] = tfbits(av1.w);
        Bc[(seg + 0) * SMS + lr] = tfbits(bv0.x);
        Bc[(seg + 1) * SMS + lr] = tfbits(bv0.y);
        Bc[(seg + 2) * SMS + lr] = tfbits(bv0.z);
        Bc[(seg + 3) * SMS + lr] = tfbits(bv0.w);
        Bc[(seg + 4) * SMS + lr] = tfbits(bv1.x);
        Bc[(seg + 5) * SMS + lr] = tfbits(bv1.y);
        Bc[(seg + 6) * SMS + lr] = tfbits(bv1.z);
        Bc[(seg + 7) * SMS + lr] = tfbits(bv1.w);
    }
    __syncthreads();

    for (int k0 = 0; k0 < CDIM; k0 += 16) {
        // Prefetch next slab into registers (hidden under compute)
        const bool next = (k0 + 16) < CDIM;
        float4 nav0, nav1, nbv0, nbv1;
        if (next) {
            nav0 = *(const float4*)&Xrow[k0 + 16 + seg];
            nav1 = *(const float4*)&Xrow[k0 + 16 + seg + 4];
            nbv0 = *(const float4*)&Wrow[k0 + 16 + seg];
            nbv1 = *(const float4*)&Wrow[k0 + 16 + seg + 4];
        }

        // Compute on current buffer
        #pragma unroll
        for (int ks = 0; ks < 16; ks += 8) {
            unsigned a[4][4], b[4][2];
            const float* a0 = Ac + (ks + tig) * SMS;
            const float* a4 = Ac + (ks + tig + 4) * SMS;
            const float* b0 = Bc + (ks + tig) * SMS;
            const float* b4 = Bc + (ks + tig + 4) * SMS;
            #pragma unroll
            for (int im = 0; im < 4; im++) {
                const int m = wm0 + im * 16 + g;
                a[im][0] = __float_as_uint(a0[m]);
                a[im][1] = __float_as_uint(a0[m + 8]);
                a[im][2] = __float_as_uint(a4[m]);
                a[im][3] = __float_as_uint(a4[m + 8]);
            }
            #pragma unroll
            for (int in_ = 0; in_ < 4; in_++) {
                const int n = wn0 + in_ * 8 + g;
                b[in_][0] = __float_as_uint(b0[n]);
                b[in_][1] = __float_as_uint(b4[n]);
            }
            #pragma unroll
            for (int im = 0; im < 4; im++)
                #pragma unroll
                for (int in_ = 0; in_ < 4; in_++)
                    mma_tf32(d[im][in_], a[im], b[in_]);
        }

        if (next) {
            // Store prefetched slab into the alternate buffer, then swap
            An[(seg + 0) * SMS + lr] = tfbits(nav0.x);
            An[(seg + 1) * SMS + lr] = tfbits(nav0.y);
            An[(seg + 2) * SMS + lr] = tfbits(nav0.z);
            An[(seg + 3) * SMS + lr] = tfbits(nav0.w);
            An[(seg + 4) * SMS + lr] = tfbits(nav1.x);
            An[(seg + 5) * SMS + lr] = tfbits(nav1.y);
            An[(seg + 6) * SMS + lr] = tfbits(nav1.z);
            An[(seg + 7) * SMS + lr] = tfbits(nav1.w);
            Bn[(seg + 0) * SMS + lr] = tfbits(nbv0.x);
            Bn[(seg + 1) * SMS + lr] = tfbits(nbv0.y);
            Bn[(seg + 2) * SMS + lr] = tfbits(nbv0.z);
            Bn[(seg + 3) * SMS + lr] = tfbits(nbv0.w);
            Bn[(seg + 4) * SMS + lr] = tfbits(nbv1.x);
            Bn[(seg + 5) * SMS + lr] = tfbits(nbv1.y);
            Bn[(seg + 6) * SMS + lr] = tfbits(nbv1.z);
            Bn[(seg + 7) * SMS + lr] = tfbits(nbv1.w);
            __syncthreads();
            float* tp;
            tp = Ac; Ac = An; An = tp;
            tp = Bc; Bc = Bn; Bn = tp;
        }
    }

    if (mode < 4) {
        float* outp = (mode == 0) ? g_Q : (mode == 1) ? g_Kw
                    : (mode == 2) ? g_Vw : g_G2;
        const int tig2 = 2 * tig;
        #pragma unroll
        for (int im = 0; im < 4; im++) {
            const int r = row0 + wm0 + im * 16 + g;
            #pragma unroll
            for (int in_ = 0; in_ < 4; in_++) {
                const int c = col0 + wn0 + in_ * 8 + tig2;
                float2 v01 = make_float2(d[im][in_][0], d[im][in_][1]);
                float2 v23 = make_float2(d[im][in_][2], d[im][in_][3]);
                if (mode == 3) {
                    const float b0 = bgate[c], b1 = bgate[c + 1];
                    v01.x += b0; v01.y += b1;
                    v23.x += b0; v23.y += b1;
                }
                *(float2*)&outp[(size_t)r * CDIM + c]       = v01;
                *(float2*)&outp[(size_t)(r + 8) * CDIM + c] = v23;
            }
        }
    } else {
        const int tig2 = 2 * tig;
        #pragma unroll
        for (int im = 0; im < 4; im++) {
            const int r = row0 + wm0 + im * 16 + g;
            #pragma unroll
            for (int in_ = 0; in_ < 4; in_++) {
                const int c = col0 + wn0 + in_ * 8 + tig2;
                const float es0 = 1.f / (1.f + __expf(-eta[c]));
                const float es1 = 1.f / (1.f + __expf(-eta[c + 1]));
                #pragma unroll
                for (int rr = 0; rr < 2; rr++) {
                    const int row = r + rr * 8;
                    const size_t i0 = (size_t)row * CDIM + c;
                    float2 uo;
                    {
                        const float logit = d[im][in_][rr * 2 + 0] + g_G2[i0];
                        const float sur   = 1.f / (1.f + __expf(-logit));
                        uo.x = es0 * sur * (g_Vw[i0] - g_retr[i0]);
                    }
                    {
                        const float logit = d[im][in_][rr * 2 + 1] + g_G2[i0 + 1];
                        const float sur   = 1.f / (1.f + __expf(-logit));
                        uo.y = es1 * sur * (g_Vw[i0 + 1] - g_retr[i0 + 1]);
                    }
                    *(float2*)&g_u[i0] = uo;
                }
            }
        }
    }
}

// ---------------------------------------------------------------------------
// Attention read + Mk update. One CTA per batch row, 512 threads.
// ---------------------------------------------------------------------------
__global__ void attn_kernel(const float* __restrict__ h,
                            const float* __restrict__ Min,
                            const float* __restrict__ Mk,
                            float* __restrict__ out)
{
    const int b    = blockIdx.x;
    const int tid  = threadIdx.x;       // 0..511
    const int warp = tid >> 5;
    const int lane = tid & 31;

    extern __shared__ float sm[];
    float* sq   = sm;                    // 512
    float* skw  = sm + 512;              // 512
    float* mkc  = sm + 1024;             // 32*512
    float* lq   = sm + 1024 + 16384;     // 32
    float* lk   = lq + 32;               // 32
    float* attn = lk + 32;               // 32
    float* ww   = attn + 32;             // 32

    sq[tid]  = g_Q [(size_t)b * CDIM + tid];
    skw[tid] = g_Kw[(size_t)b * CDIM + tid];
    __syncthreads();

    const float4* sq4  = (const float4*)sq;
    const float4* sk4  = (const float4*)skw;
    float4*       mkc4 = (float4*)mkc;
    const float4* mkrow = (const float4*)(Mk + (size_t)b * SLOTS * CDIM);

    #pragma unroll
    for (int i = 0; i < 2; i++) {
        const int m = warp + 16 * i;
        float dq = 0.f, dk = 0.f;
        #pragma unroll
        for (int j = 0; j < 4; j++) {
            const int g = lane + 32 * j;
            float4 v  = mkrow[m * 128 + g];
            float4 qv = sq4[g];
            float4 kv = sk4[g];
            dq += v.x * qv.x + v.y * qv.y + v.z * qv.z + v.w * qv.w;
            dk += v.x * kv.x + v.y * kv.y + v.z * kv.z + v.w * kv.w;
            mkc4[m * 128 + g] = v;
        }
        #pragma unroll
        for (int o = 16; o > 0; o >>= 1) {
            dq += __shfl_xor_sync(0xffffffffu, dq, o);
            dk += __shfl_xor_sync(0xffffffffu, dk, o);
        }
        if (lane == 0) { lq[m] = dq * INV_SQRT_C; lk[m] = dk * INV_SQRT_C; }
    }
    __syncthreads();

    if (tid < 32) {
        float vq = lq[tid], vk = lk[tid];
        float mq = vq, mk2 = vk;
        #pragma unroll
        for (int o = 16; o > 0; o >>= 1) {
            mq  = fmaxf(mq,  __shfl_xor_sync(0xffffffffu, mq,  o));
            mk2 = fmaxf(mk2, __shfl_xor_sync(0xffffffffu, mk2, o));
        }
        float eq = __expf(vq - mq);
        float ek = __expf(vk - mk2);
        float sumq = eq, sumk = ek;
        #pragma unroll
        for (int o = 16; o > 0; o >>= 1) {
            sumq += __shfl_xor_sync(0xffffffffu, sumq, o);
            sumk += __shfl_xor_sync(0xffffffffu, sumk, o);
        }
        const float a = eq / sumq;
        const float w = ek / sumk;
        attn[tid] = a;
        ww[tid]   = w;
        g_ww[b * SLOTS + tid] = w;
    }
    __syncthreads();

    // Mk_new = Mk + ww*KEY_LR*(write_k - Mk), from SMEM cache
    float4* out_mk4 = (float4*)(out + OUT_OFF_MK + (size_t)b * SLOTS * CDIM);
    for (int idx = tid; idx < SLOTS * 128; idx += 512) {
        const int m = idx >> 7;
        const int g = idx & 127;
        float4 v  = mkc4[idx];
        float4 kv = sk4[g];
        const float w = ww[m] * KEY_LR;
        float4 r;
        r.x = v.x + w * (kv.x - v.x);
        r.y = v.y + w * (kv.y - v.y);
        r.z = v.z + w * (kv.z - v.z);
        r.w = v.w + w * (kv.w - v.w);
        out_mk4[idx] = r;
    }

    // retrieved[c] = sum_m attn[m] * M[b,m,c];  out = h + retrieved
    const float* Mrow = Min + (size_t)b * SLOTS * CDIM;
    float acc = 0.f;
    #pragma unroll
    for (int m = 0; m < SLOTS; m++)
        acc = fmaf(attn[m], Mrow[m * CDIM + tid], acc);
    g_retr[(size_t)b * CDIM + tid] = acc;
    out[OUT_OFF_OUT + (size_t)b * CDIM + tid] =
        h[(size_t)b * CDIM + tid] + acc;
}

// ---------------------------------------------------------------------------
// M_new = M + ww[m] * u[c]. One CTA per batch row, 256 threads.
// ---------------------------------------------------------------------------
__global__ void mupdate_kernel(const float* __restrict__ Min,
                               float* __restrict__ out)
{
    const int b   = blockIdx.x;
    const int tid = threadIdx.x;        // 0..255
    __shared__ float su[CDIM];
    __shared__ float sww[SLOTS];
    su[tid]       = g_u[(size_t)b * CDIM + tid];
    su[tid + 256] = g_u[(size_t)b * CDIM + tid + 256];
    if (tid < SLOTS) sww[tid] = g_ww[b * SLOTS + tid];
    __syncthreads();

    const float4* M4   = (const float4*)(Min + (size_t)b * SLOTS * CDIM);
    float4*       out4 = (float4*)(out + OUT_OFF_M + (size_t)b * SLOTS * CDIM);
    const float4* su4  = (const float4*)su;

    #pragma unroll 4
    for (int idx = tid; idx < SLOTS * 128; idx += 256) {
        const int m = idx >> 7;
        const int g = idx & 127;
        float4 mv = M4[idx];
        float4 uv = su4[g];
        const float w = sww[m];
        float4 r;
        r.x = fmaf(w, uv.x, mv.x);
        r.y = fmaf(w, uv.y, mv.y);
        r.z = fmaf(w, uv.z, mv.z);
        r.w = fmaf(w, uv.w, mv.w);
        out4[idx] = r;
    }
}

// ---------------------------------------------------------------------------
extern "C" void kernel_launch(void* const* d_in, const int* in_sizes, int n_in,
                              void* d_out, int out_size)
{
    (void)in_sizes; (void)n_in; (void)out_size;
    const float* h      = (const float*)d_in[0];
    const float* pooled = (const float*)d_in[1];
    const float* M      = (const float*)d_in[2];
    const float* Mk     = (const float*)d_in[3];
    const float* Wq     = (const float*)d_in[4];
    const float* Wk     = (const float*)d_in[5];
    const float* Wv     = (const float*)d_in[6];
    const float* Wg     = (const float*)d_in[7];
    const float* bg     = (const float*)d_in[8];
    const float* eta    = (const float*)d_in[9];
    float* out = (float*)d_out;

    const int smem_attn = (1024 + SLOTS * CDIM + 128) * (int)sizeof(float); // 70144 B
    cudaFuncSetAttribute(attn_kernel,
                         cudaFuncAttributeMaxDynamicSharedMemorySize, smem_attn);

    // 1) Q, K, V, G2 projections (tf32 tensor cores, double-buffered)
    dim3 g1(CDIM / 128, BDIM / 128, 4);
    gemm_tf32_kernel<<<g1, 256>>>(h, pooled, Wq, Wk, Wv, Wg, bg, eta, 0);

    // 2) attention read + Mk update + out
    attn_kernel<<<BDIM, 512, smem_attn>>>(h, M, Mk, out);

    // 3) gate GEMM -> u
    dim3 g3(CDIM / 128, BDIM / 128, 1);
    gemm_tf32_kernel<<<g3, 256>>>(h, pooled, Wq, Wk, Wv, Wg, bg, eta, 4);

    // 4) M update
    mupdate_kernel<<<BDIM, 256>>>(M, out);
}